// round 13
// baseline (speedup 1.0000x reference)
#include <cuda_runtime.h>

#define BB 8
#define TT 4096
#define DD 256
#define HH 256
#define G4 1024   // 4*H
#define CLUS 8
#define NTHR 512

// 128 MB scratch for x@Wi+b, PERMUTED layout:
// element (b, row, col) with col = 32g + 256j + m  stored at
// g_xWi[b][row][g*128 + j*32 + m]   (g = slice 0..7, j = gate, m = 0..31)
__device__ float    g_xWi[BB * TT * G4];
__device__ unsigned g_prog[BB * CLUS];   // rows produced per (batch, slice)

// ---------------------------------------------------------------------------
__global__ void init_kernel() {
    if (threadIdx.x < BB * CLUS) g_prog[threadIdx.x] = 0u;
}

// ---------------------------------------------------------------------------
__device__ __forceinline__ unsigned ld_acq(const unsigned* p) {
    unsigned v;
    asm volatile("ld.acquire.gpu.global.u32 %0, [%1];"
                 : "=r"(v) : "l"(p) : "memory");
    return v;
}

// ---------------------------------------------------------------------------
// Fused kernel: 16 clusters of 8 CTAs x 512 threads.
//   clusters 0..7  : recurrence for batch = cluster_id (R6 body verbatim)
//   clusters 8..15 : xWi producer for batch = cluster_id-8, slice g = rank
// Producer emits rows in the exact consumption order src(i) and publishes
// via red.release on g_prog; consumer uses a stale cached flag refreshed
// with one non-blocking acquire load per step (latency hidden), spinning
// only if the producer is behind (never, in steady state: ~600 vs ~2400
// cyc/row). All 128 CTAs are co-resident in wave 1 -> no deadlock.
// ---------------------------------------------------------------------------
__global__ void __launch_bounds__(NTHR, 1) __cluster_dims__(CLUS, 1, 1)
fused_kernel(const float* __restrict__ x,
             const float* __restrict__ Wi,
             const float* __restrict__ Wh,
             const float* __restrict__ bias,
             const int* __restrict__ seqlen,
             float* __restrict__ y) {
    __shared__ float  h_s[2][HH];
    __shared__ float4 v_s[32];
    __shared__ float  xs[2][DD];

    const int cid  = blockIdx.x / CLUS;
    const int rank = blockIdx.x % CLUS;

    // =====================================================================
    // Producer clusters
    // =====================================================================
    if (cid >= BB) {
        const int b = cid - BB;
        const int g = rank;
        const int tid = threadIdx.x;
        const int c   = tid >> 2;            // col_local 0..127
        const int dq  = tid & 3;             // d-quarter (64 floats)
        const int j   = c >> 5, m = c & 31;
        const int wcol = 32 * g + 256 * j + m;   // original Wi column

        // Wi slice in registers: 32 f32x2 pairs over my 64-d range
        unsigned long long wi2[32];
#pragma unroll
        for (int i = 0; i < 32; i++) {
            int d = dq * 64 + 2 * i;
            float lo = Wi[(size_t)d * G4 + wcol];
            float hi = Wi[(size_t)(d + 1) * G4 + wcol];
            asm("mov.b64 %0, {%1, %2};" : "=l"(wi2[i]) : "f"(lo), "f"(hi));
        }
        const float bcol = bias[wcol];
        const int L = seqlen[b];
        const float* xb   = x + (size_t)b * TT * DD;
        float*       outb = g_xWi + (size_t)b * TT * G4;
        unsigned*    prog = &g_prog[b * CLUS + g];

        // stage row for i=0
        {
            int row0 = (TT - 1 + L) & (TT - 1);
            if (tid < 64)
                ((float4*)xs[0])[tid] =
                    ((const float4*)(xb + (size_t)row0 * DD))[tid];
        }
        __syncthreads();

        for (int i = 0; i < TT; i++) {
            float4 xn = make_float4(0.f, 0.f, 0.f, 0.f);
            if (tid < 64 && i + 1 < TT) {
                int rown = (TT - 2 - i + L) & (TT - 1);
                xn = ((const float4*)(xb + (size_t)rown * DD))[tid];
            }

            const unsigned long long* xp =
                (const unsigned long long*)&xs[i & 1][dq * 64];
            unsigned long long a0 = 0ull, a1 = 0ull, a2 = 0ull, a3 = 0ull;
            unsigned long long h2[16];
#pragma unroll
            for (int k = 0; k < 16; k++) h2[k] = xp[k];
#pragma unroll
            for (int k = 0; k < 4; k++) {
                asm("fma.rn.f32x2 %0, %1, %2, %0;"
                    : "+l"(a0) : "l"(h2[4 * k + 0]), "l"(wi2[4 * k + 0]));
                asm("fma.rn.f32x2 %0, %1, %2, %0;"
                    : "+l"(a1) : "l"(h2[4 * k + 1]), "l"(wi2[4 * k + 1]));
                asm("fma.rn.f32x2 %0, %1, %2, %0;"
                    : "+l"(a2) : "l"(h2[4 * k + 2]), "l"(wi2[4 * k + 2]));
                asm("fma.rn.f32x2 %0, %1, %2, %0;"
                    : "+l"(a3) : "l"(h2[4 * k + 3]), "l"(wi2[4 * k + 3]));
            }
#pragma unroll
            for (int k = 0; k < 16; k++) h2[k] = xp[16 + k];
#pragma unroll
            for (int k = 0; k < 4; k++) {
                asm("fma.rn.f32x2 %0, %1, %2, %0;"
                    : "+l"(a0) : "l"(h2[4 * k + 0]), "l"(wi2[16 + 4 * k + 0]));
                asm("fma.rn.f32x2 %0, %1, %2, %0;"
                    : "+l"(a1) : "l"(h2[4 * k + 1]), "l"(wi2[16 + 4 * k + 1]));
                asm("fma.rn.f32x2 %0, %1, %2, %0;"
                    : "+l"(a2) : "l"(h2[4 * k + 2]), "l"(wi2[16 + 4 * k + 2]));
                asm("fma.rn.f32x2 %0, %1, %2, %0;"
                    : "+l"(a3) : "l"(h2[4 * k + 3]), "l"(wi2[16 + 4 * k + 3]));
            }
            unsigned long long s01, s23, sall;
            asm("add.rn.f32x2 %0, %1, %2;" : "=l"(s01)  : "l"(a0), "l"(a1));
            asm("add.rn.f32x2 %0, %1, %2;" : "=l"(s23)  : "l"(a2), "l"(a3));
            asm("add.rn.f32x2 %0, %1, %2;" : "=l"(sall) : "l"(s01), "l"(s23));
            float lo, hi;
            asm("mov.b64 {%0, %1}, %2;" : "=f"(lo), "=f"(hi) : "l"(sall));
            float s = lo + hi;
            s += __shfl_xor_sync(0xffffffffu, s, 1);
            s += __shfl_xor_sync(0xffffffffu, s, 2);

            int row = (TT - 1 - i + L) & (TT - 1);
            if (dq == 0)
                outb[(size_t)row * G4 + g * 128 + c] = s + bcol;

            if (tid < 64 && i + 1 < TT)
                ((float4*)xs[(i + 1) & 1])[tid] = xn;
            __syncthreads();   // STG + STS visible before publish/reuse
            if (tid == 0)
                asm volatile("red.release.gpu.global.add.u32 [%0], %1;"
                             :: "l"(prog), "r"(1u) : "memory");
        }
        return;
    }

    // =====================================================================
    // Recurrence clusters (R6 body; only the xWi addressing + flag changed)
    // =====================================================================
    const int b = cid;
    const int r = rank;
    const int w = threadIdx.x >> 5;
    const int l = threadIdx.x & 31;
    const int k0 = r * 32 + 2 * w;

    unsigned long long wh2[8][4];
#pragma unroll
    for (int j = 0; j < 8; j++) {
        int col = (j < 4) ? (k0 + 256 * j) : (k0 + 1 + 256 * (j - 4));
#pragma unroll
        for (int dd = 0; dd < 4; dd++) {
            int d = l * 8 + dd * 2;
            float lo = Wh[(size_t)d * G4 + col];
            float hi = Wh[(size_t)(d + 1) * G4 + col];
            asm("mov.b64 %0, {%1, %2};" : "=l"(wh2[j][dd]) : "f"(lo), "f"(hi));
        }
    }

    for (int i = threadIdx.x; i < HH; i += NTHR) h_s[0][i] = 0.f;
    __syncthreads();
    asm volatile("barrier.cluster.arrive.aligned;" ::: "memory");
    asm volatile("barrier.cluster.wait.aligned;"   ::: "memory");

    const int L = seqlen[b];
    float*    yb   = y + (size_t)b * TT * HH;
    const float* xWib = g_xWi + (size_t)b * TT * G4;
    const unsigned* prog = &g_prog[b * CLUS + r];

    const int myk = r * 32 + l;
    float c_state = 0.f;

    unsigned int hs_addr;
    asm("{ .reg .u64 t; cvta.to.shared.u64 t, %1; cvt.u32.u64 %0, t; }"
        : "=r"(hs_addr) : "l"((void*)h_s));
    unsigned int slot0 = hs_addr + (unsigned)myk * 4u;
    unsigned int peer[CLUS];
#pragma unroll
    for (int p = 0; p < CLUS; p++)
        asm("mapa.shared::cluster.u32 %0, %1, %2;"
            : "=r"(peer[p]) : "r"(slot0), "r"(p));

    // warp0: blocking wait for row 0, then preload (permuted: 4x128B)
    unsigned pv = 0;
    float xc0 = 0.f, xc1 = 0.f, xc2 = 0.f, xc3 = 0.f;
    if (w == 0) {
        while (pv < 1u) pv = ld_acq(prog);
        int src0 = (TT - 1 + L) & (TT - 1);
        const float* p = xWib + (size_t)src0 * G4 + r * 128 + l;
        xc0 = p[0]; xc1 = p[32]; xc2 = p[64]; xc3 = p[96];
    }

    const int cidx = (l >> 2) & 7;
    const int h_local = 2 * w + (cidx >> 2);
    const int gate    = cidx & 3;
    const bool storer = ((l & 3) == 0);

    for (int t = 0; t < TT; t++) {
        float xn0 = 0.f, xn1 = 0.f, xn2 = 0.f, xn3 = 0.f;
        if (w == 0 && t + 1 < TT) {
            while (pv < (unsigned)(t + 2))        // stale-check; rarely spins
                pv = ld_acq(prog);
            int srcn = (TT - 2 - t + L) & (TT - 1);
            const float* p = xWib + (size_t)srcn * G4 + r * 128 + l;
            xn0 = p[0]; xn1 = p[32]; xn2 = p[64]; xn3 = p[96];
            pv = ld_acq(prog);                    // non-blocking refresh
        }

        const unsigned long long* hp =
            (const unsigned long long*)&h_s[t & 1][l * 8];
        unsigned long long h2[4];
        h2[0] = hp[0]; h2[1] = hp[1]; h2[2] = hp[2]; h2[3] = hp[3];

        unsigned long long acc[8];
#pragma unroll
        for (int j = 0; j < 8; j++) acc[j] = 0ull;
#pragma unroll
        for (int dd = 0; dd < 4; dd++)
#pragma unroll
            for (int j = 0; j < 8; j++)
                asm("fma.rn.f32x2 %0, %1, %2, %0;"
                    : "+l"(acc[j]) : "l"(h2[dd]), "l"(wh2[j][dd]));

        float ps[8];
#pragma unroll
        for (int j = 0; j < 8; j++) {
            float lo, hi;
            asm("mov.b64 {%0, %1}, %2;" : "=f"(lo), "=f"(hi) : "l"(acc[j]));
            ps[j] = lo + hi;
        }

        float u0, u1, u2, u3;
        {
            float a0 = __shfl_xor_sync(0xffffffffu, ps[0], 16);
            float a4 = __shfl_xor_sync(0xffffffffu, ps[4], 16);
            float a1 = __shfl_xor_sync(0xffffffffu, ps[1], 16);
            float a5 = __shfl_xor_sync(0xffffffffu, ps[5], 16);
            float a2 = __shfl_xor_sync(0xffffffffu, ps[2], 16);
            float a6 = __shfl_xor_sync(0xffffffffu, ps[6], 16);
            float a3 = __shfl_xor_sync(0xffffffffu, ps[3], 16);
            float a7 = __shfl_xor_sync(0xffffffffu, ps[7], 16);
            bool hi = (l & 16);
            u0 = hi ? (ps[4] + a4) : (ps[0] + a0);
            u1 = hi ? (ps[5] + a5) : (ps[1] + a1);
            u2 = hi ? (ps[6] + a6) : (ps[2] + a2);
            u3 = hi ? (ps[7] + a7) : (ps[3] + a3);
        }
        float t0, t1;
        {
            float a0 = __shfl_xor_sync(0xffffffffu, u0, 8);
            float a2 = __shfl_xor_sync(0xffffffffu, u2, 8);
            float a1 = __shfl_xor_sync(0xffffffffu, u1, 8);
            float a3 = __shfl_xor_sync(0xffffffffu, u3, 8);
            bool hi = (l & 8);
            t0 = hi ? (u2 + a2) : (u0 + a0);
            t1 = hi ? (u3 + a3) : (u1 + a1);
        }
        float s;
        {
            float a0 = __shfl_xor_sync(0xffffffffu, t0, 4);
            float a1 = __shfl_xor_sync(0xffffffffu, t1, 4);
            s = (l & 4) ? (t1 + a1) : (t0 + a0);
        }
        s += __shfl_xor_sync(0xffffffffu, s, 2);
        s += __shfl_xor_sync(0xffffffffu, s, 1);

        if (storer) ((float*)&v_s[h_local])[gate] = s;
        __syncthreads();

        if (w == 0) {
            float4 vv = v_s[l];
            float zi = vv.x + xc0;
            float zf = vv.y + xc1;
            float zg = vv.z + xc2;
            float zo = vv.w + xc3;
            float si = 1.f / (1.f + __expf(-zi));
            float sf = 1.f / (1.f + __expf(-zf));
            float so = 1.f / (1.f + __expf(-zo));
            float tg = 2.f / (1.f + __expf(-2.f * zg)) - 1.f;
            c_state  = sf * c_state + si * tg;
            float tc = 2.f / (1.f + __expf(-2.f * c_state)) - 1.f;
            float nh = so * tc;

            if (t < TT - 1) {
                unsigned int bufoff = ((t + 1) & 1) ? (unsigned)HH * 4u : 0u;
#pragma unroll
                for (int p = 0; p < CLUS; p++)
                    asm volatile("st.shared::cluster.f32 [%0], %1;"
                                 :: "r"(peer[p] + bufoff), "f"(nh) : "memory");
            }

            const int src = (TT - 1 - t + L) & (TT - 1);
            yb[(size_t)src * HH + myk] = nh;

            xc0 = xn0; xc1 = xn1; xc2 = xn2; xc3 = xn3;
        }

        if (t < TT - 1) {
            asm volatile("barrier.cluster.arrive.aligned;" ::: "memory");
            asm volatile("barrier.cluster.wait.aligned;"   ::: "memory");
        }
    }
}

// ---------------------------------------------------------------------------
extern "C" void kernel_launch(void* const* d_in, const int* in_sizes, int n_in,
                              void* d_out, int out_size) {
    const float* x    = (const float*)d_in[0];
    const float* Wi   = (const float*)d_in[1];
    const float* Wh   = (const float*)d_in[2];
    const float* bias = (const float*)d_in[3];
    const int*   seql = (const int*)d_in[4];
    float*       y    = (float*)d_out;

    init_kernel<<<1, 64>>>();
    fused_kernel<<<2 * BB * CLUS, NTHR>>>(x, Wi, Wh, bias, seql, y);
}

// round 14
// speedup vs baseline: 3.0261x; 3.0261x over previous
#include <cuda_runtime.h>

#define BB 8
#define TT 4096
#define DD 256
#define HH 256
#define G4 1024   // 4*H
#define CLUS 8
#define NTHR 512

// 128 MB scratch for x@Wi+b, [B*T, 4H]
__device__ float g_xWi[BB * TT * G4];

// ---------------------------------------------------------------------------
// GEMM: g_xWi = x[B*T, D] @ Wi[D, 4H] + b
// ---------------------------------------------------------------------------
__global__ void __launch_bounds__(256) gemm_kernel(const float* __restrict__ x,
                                                   const float* __restrict__ Wi,
                                                   const float* __restrict__ bias) {
    __shared__ float As[16][132];
    __shared__ float Bs[16][64];

    int tid = threadIdx.x;
    int bm = blockIdx.y, bn = blockIdx.x;
    const float* Ablk = x + (size_t)bm * 128 * DD;
    const float* Bblk = Wi + bn * 64;

    int ty = tid >> 4;
    int tx = tid & 15;

    float acc[8][4];
#pragma unroll
    for (int i = 0; i < 8; i++)
#pragma unroll
        for (int j = 0; j < 4; j++) acc[i][j] = 0.f;

    for (int k0 = 0; k0 < DD; k0 += 16) {
#pragma unroll
        for (int i = 0; i < 2; i++) {
            int f4  = tid * 2 + i;
            int row = f4 >> 2;
            int kq  = (f4 & 3) * 4;
            float4 v = *(const float4*)(Ablk + (size_t)row * DD + k0 + kq);
            As[kq + 0][row] = v.x;
            As[kq + 1][row] = v.y;
            As[kq + 2][row] = v.z;
            As[kq + 3][row] = v.w;
        }
        {
            int kk = tid >> 4;
            int nc = (tid & 15) * 4;
            *(float4*)&Bs[kk][nc] =
                *(const float4*)(Bblk + (size_t)(k0 + kk) * G4 + nc);
        }
        __syncthreads();

#pragma unroll
        for (int kk = 0; kk < 16; kk++) {
            float a[8], bb[4];
            *(float4*)(a)     = *(float4*)&As[kk][ty * 8];
            *(float4*)(a + 4) = *(float4*)&As[kk][ty * 8 + 4];
            *(float4*)(bb)    = *(float4*)&Bs[kk][tx * 4];
#pragma unroll
            for (int i = 0; i < 8; i++)
#pragma unroll
                for (int j = 0; j < 4; j++) acc[i][j] += a[i] * bb[j];
        }
        __syncthreads();
    }

    int col = bn * 64 + tx * 4;
    float4 bv = *(const float4*)(bias + col);
#pragma unroll
    for (int i = 0; i < 8; i++) {
        int row = bm * 128 + ty * 8 + i;
        float4 o;
        o.x = acc[i][0] + bv.x;
        o.y = acc[i][1] + bv.y;
        o.z = acc[i][2] + bv.z;
        o.w = acc[i][3] + bv.w;
        *(float4*)(g_xWi + (size_t)row * G4 + col) = o;
    }
}

// ---------------------------------------------------------------------------
// Recurrent kernel: 1 cluster (8 CTAs x 512 thr) per batch; grid = 64 CTAs.
// CTA rank r owns h-indices [32r, 32r+32). Warp w handles the 8 gate columns
// of k0=32r+2w, k0+1; lane owns a d-chunk of 8 (Wh in regs, packed f32x2).
// DISTRIBUTED GATE PHASE (no __syncthreads in the loop):
//  - full-split butterfly leaves column q's COMPLETE sum in quad q
//  - xWi pre-acts: 1 LDG/warp (lanes 0-7, one per column), routed with
//    1 shfl (src=(l>>2)&7) and added post-butterfly
//  - 4 shfl.idx gathers (src=(l&16)+4j) put the 4 gate sums in lanes 0/16,
//    which run the gate math for k0/k0+1 (c_state lives there), broadcast
//    new h to all 8 CTAs via DSMEM, and store y
//  - every warp reaches barrier.cluster.arrive independently; split
//    arrive/wait with the y store + register swap inside the window
// No DSMEM store after the final barrier (peer-exit race).
// ---------------------------------------------------------------------------
__global__ void __launch_bounds__(NTHR, 1) __cluster_dims__(CLUS, 1, 1)
rnn_kernel(const float* __restrict__ Wh,
           const int* __restrict__ seqlen,
           float* __restrict__ y) {
    __shared__ float h_s[2][HH];

    const int b = blockIdx.x / CLUS;
    const int r = blockIdx.x % CLUS;
    const int w = threadIdx.x >> 5;
    const int l = threadIdx.x & 31;
    const int k0 = r * 32 + 2 * w;

    // ---- preload Wh slice as packed f32x2 pairs over d ----
    // j<4: gate j of column k0 ; j>=4: gate j-4 of column k0+1
    unsigned long long wh2[8][4];
#pragma unroll
    for (int j = 0; j < 8; j++) {
        int col = (j < 4) ? (k0 + 256 * j) : (k0 + 1 + 256 * (j - 4));
#pragma unroll
        for (int dd = 0; dd < 4; dd++) {
            int d = l * 8 + dd * 2;
            float lo = Wh[(size_t)d * G4 + col];
            float hi = Wh[(size_t)(d + 1) * G4 + col];
            asm("mov.b64 %0, {%1, %2};" : "=l"(wh2[j][dd]) : "f"(lo), "f"(hi));
        }
    }

    // ---- zero initial hidden state (buffer 0) ----
    for (int i = threadIdx.x; i < HH; i += NTHR) h_s[0][i] = 0.f;
    __syncthreads();
    asm volatile("barrier.cluster.arrive.aligned;" ::: "memory");
    asm volatile("barrier.cluster.wait.aligned;"   ::: "memory");

    const int L = seqlen[b];
    const float* xWib = g_xWi + (size_t)b * TT * G4;
    float*       yb   = y + (size_t)b * TT * HH;

    // ---- per-warp gate lanes: lane 0 -> k0, lane 16 -> k0+1 ----
    const int  myk       = k0 + ((l >> 4) & 1);
    const bool gate_lane = ((l & 15) == 0);
    float c_state = 0.f;

    // DSMEM peer addresses for h slot myk (buffer 0)
    unsigned int hs_addr;
    asm("{ .reg .u64 t; cvta.to.shared.u64 t, %1; cvt.u32.u64 %0, t; }"
        : "=r"(hs_addr) : "l"((void*)h_s));
    unsigned int slot0 = hs_addr + (unsigned)myk * 4u;
    unsigned int peer[CLUS];
#pragma unroll
    for (int p = 0; p < CLUS; p++)
        asm("mapa.shared::cluster.u32 %0, %1, %2;"
            : "=r"(peer[p]) : "r"(slot0), "r"(p));

    // xWi column for loader lanes 0..7 (column c of this warp)
    const int c    = l & 7;
    const int gcol = (c < 4) ? (k0 + 256 * c) : (k0 + 1 + 256 * (c - 4));

    // preload xWi for t=0 (lanes 0..7: one LDG per warp)
    float xc = 0.f;
    if (l < 8) {
        int src0 = (TT - 1 + L) & (TT - 1);
        xc = xWib[(size_t)src0 * G4 + gcol];
    }

    const int base = l & 16;       // gather base for this lane's h-index

    for (int t = 0; t < TT; t++) {
        // prefetch next step's xWi (lanes 0..7, 1 LDG/warp)
        float xn = 0.f;
        if (l < 8 && t + 1 < TT) {
            int srcn = (TT - 2 - t + L) & (TT - 1);
            xn = xWib[(size_t)srcn * G4 + gcol];
        }

        // load previous h (own SMEM) as packed pairs
        const unsigned long long* hp =
            (const unsigned long long*)&h_s[t & 1][l * 8];
        unsigned long long h2[4];
        h2[0] = hp[0]; h2[1] = hp[1]; h2[2] = hp[2]; h2[3] = hp[3];

        // 8 packed-f32x2 accumulators (one per gate column)
        unsigned long long acc[8];
#pragma unroll
        for (int j = 0; j < 8; j++) acc[j] = 0ull;
#pragma unroll
        for (int dd = 0; dd < 4; dd++)
#pragma unroll
            for (int j = 0; j < 8; j++)
                asm("fma.rn.f32x2 %0, %1, %2, %0;"
                    : "+l"(acc[j]) : "l"(h2[dd]), "l"(wh2[j][dd]));

        // horizontal pair-sum -> ps[8]
        float ps[8];
#pragma unroll
        for (int j = 0; j < 8; j++) {
            float lo, hi;
            asm("mov.b64 {%0, %1}, %2;" : "=f"(lo), "=f"(hi) : "l"(acc[j]));
            ps[j] = lo + hi;
        }

        // full-split butterfly: 16 SHFL, 5 levels -> quad q holds column q
        float u0, u1, u2, u3;
        {
            float a0 = __shfl_xor_sync(0xffffffffu, ps[0], 16);
            float a4 = __shfl_xor_sync(0xffffffffu, ps[4], 16);
            float a1 = __shfl_xor_sync(0xffffffffu, ps[1], 16);
            float a5 = __shfl_xor_sync(0xffffffffu, ps[5], 16);
            float a2 = __shfl_xor_sync(0xffffffffu, ps[2], 16);
            float a6 = __shfl_xor_sync(0xffffffffu, ps[6], 16);
            float a3 = __shfl_xor_sync(0xffffffffu, ps[3], 16);
            float a7 = __shfl_xor_sync(0xffffffffu, ps[7], 16);
            bool hi = (l & 16);
            u0 = hi ? (ps[4] + a4) : (ps[0] + a0);
            u1 = hi ? (ps[5] + a5) : (ps[1] + a1);
            u2 = hi ? (ps[6] + a6) : (ps[2] + a2);
            u3 = hi ? (ps[7] + a7) : (ps[3] + a3);
        }
        float t0, t1;
        {
            float a0 = __shfl_xor_sync(0xffffffffu, u0, 8);
            float a2 = __shfl_xor_sync(0xffffffffu, u2, 8);
            float a1 = __shfl_xor_sync(0xffffffffu, u1, 8);
            float a3 = __shfl_xor_sync(0xffffffffu, u3, 8);
            bool hi = (l & 8);
            t0 = hi ? (u2 + a2) : (u0 + a0);
            t1 = hi ? (u3 + a3) : (u1 + a1);
        }
        float s;
        {
            float a0 = __shfl_xor_sync(0xffffffffu, t0, 4);
            float a1 = __shfl_xor_sync(0xffffffffu, t1, 4);
            s = (l & 4) ? (t1 + a1) : (t0 + a0);
        }
        s += __shfl_xor_sync(0xffffffffu, s, 2);
        s += __shfl_xor_sync(0xffffffffu, s, 1);

        // add xWi pre-activation (route from loader lane = my quad index)
        float xq = __shfl_sync(0xffffffffu, xc, (l >> 2) & 7);
        s += xq;

        // gather the 4 gate sums into lanes 0 (k0) and 16 (k0+1)
        float g0 = __shfl_sync(0xffffffffu, s, base + 0);
        float g1 = __shfl_sync(0xffffffffu, s, base + 4);
        float g2 = __shfl_sync(0xffffffffu, s, base + 8);
        float g3 = __shfl_sync(0xffffffffu, s, base + 12);

        float nh = 0.f;
        if (gate_lane) {
            float si = 1.f / (1.f + __expf(-g0));
            float sf = 1.f / (1.f + __expf(-g1));
            float tg = 2.f / (1.f + __expf(-2.f * g2)) - 1.f;
            float so = 1.f / (1.f + __expf(-g3));
            c_state  = sf * c_state + si * tg;
            float tc = 2.f / (1.f + __expf(-2.f * c_state)) - 1.f;
            nh = so * tc;

            // broadcast new h to every CTA — never on the last step
            if (t < TT - 1) {
                unsigned int bufoff = ((t + 1) & 1) ? (unsigned)HH * 4u : 0u;
#pragma unroll
                for (int p = 0; p < CLUS; p++)
                    asm volatile("st.shared::cluster.f32 [%0], %1;"
                                 :: "r"(peer[p] + bufoff), "f"(nh) : "memory");
            }
        }

        if (t < TT - 1)
            asm volatile("barrier.cluster.arrive.aligned;" ::: "memory");

        // inside the barrier window: y store + register swap
        if (gate_lane) {
            const int src = (TT - 1 - t + L) & (TT - 1);
            yb[(size_t)src * HH + myk] = nh;
        }
        xc = xn;

        if (t < TT - 1)
            asm volatile("barrier.cluster.wait.aligned;" ::: "memory");
    }
}

// ---------------------------------------------------------------------------
extern "C" void kernel_launch(void* const* d_in, const int* in_sizes, int n_in,
                              void* d_out, int out_size) {
    const float* x    = (const float*)d_in[0];
    const float* Wi   = (const float*)d_in[1];
    const float* Wh   = (const float*)d_in[2];
    const float* bias = (const float*)d_in[3];
    const int*   seql = (const int*)d_in[4];
    float*       y    = (float*)d_out;

    gemm_kernel<<<dim3(G4 / 64, (BB * TT) / 128), 256>>>(x, Wi, bias);
    rnn_kernel<<<BB * CLUS, NTHR>>>(Wh, seql, y);
}

// round 15
// speedup vs baseline: 3.8568x; 1.2745x over previous
#include <cuda_runtime.h>

#define BB 8
#define TT 4096
#define DD 256
#define HH 256
#define G4 1024   // 4*H
#define CLUS 8
#define NTHR 512

// 128 MB scratch for x@Wi+b, [B*T, 4H]
__device__ float g_xWi[BB * TT * G4];

// ---------------------------------------------------------------------------
// GEMM: g_xWi = x[B*T, D] @ Wi[D, 4H] + b
// ---------------------------------------------------------------------------
__global__ void __launch_bounds__(256) gemm_kernel(const float* __restrict__ x,
                                                   const float* __restrict__ Wi,
                                                   const float* __restrict__ bias) {
    __shared__ float As[16][132];
    __shared__ float Bs[16][64];

    int tid = threadIdx.x;
    int bm = blockIdx.y, bn = blockIdx.x;
    const float* Ablk = x + (size_t)bm * 128 * DD;
    const float* Bblk = Wi + bn * 64;

    int ty = tid >> 4;
    int tx = tid & 15;

    float acc[8][4];
#pragma unroll
    for (int i = 0; i < 8; i++)
#pragma unroll
        for (int j = 0; j < 4; j++) acc[i][j] = 0.f;

    for (int k0 = 0; k0 < DD; k0 += 16) {
#pragma unroll
        for (int i = 0; i < 2; i++) {
            int f4  = tid * 2 + i;
            int row = f4 >> 2;
            int kq  = (f4 & 3) * 4;
            float4 v = *(const float4*)(Ablk + (size_t)row * DD + k0 + kq);
            As[kq + 0][row] = v.x;
            As[kq + 1][row] = v.y;
            As[kq + 2][row] = v.z;
            As[kq + 3][row] = v.w;
        }
        {
            int kk = tid >> 4;
            int nc = (tid & 15) * 4;
            *(float4*)&Bs[kk][nc] =
                *(const float4*)(Bblk + (size_t)(k0 + kk) * G4 + nc);
        }
        __syncthreads();

#pragma unroll
        for (int kk = 0; kk < 16; kk++) {
            float a[8], bb[4];
            *(float4*)(a)     = *(float4*)&As[kk][ty * 8];
            *(float4*)(a + 4) = *(float4*)&As[kk][ty * 8 + 4];
            *(float4*)(bb)    = *(float4*)&Bs[kk][tx * 4];
#pragma unroll
            for (int i = 0; i < 8; i++)
#pragma unroll
                for (int j = 0; j < 4; j++) acc[i][j] += a[i] * bb[j];
        }
        __syncthreads();
    }

    int col = bn * 64 + tx * 4;
    float4 bv = *(const float4*)(bias + col);
#pragma unroll
    for (int i = 0; i < 8; i++) {
        int row = bm * 128 + ty * 8 + i;
        float4 o;
        o.x = acc[i][0] + bv.x;
        o.y = acc[i][1] + bv.y;
        o.z = acc[i][2] + bv.z;
        o.w = acc[i][3] + bv.w;
        *(float4*)(g_xWi + (size_t)row * G4 + col) = o;
    }
}

// ---------------------------------------------------------------------------
// Recurrent kernel: 1 cluster (8 CTAs x 512 thr) per batch; grid = 64 CTAs.
// CTA rank r owns h-indices [32r, 32r+32). Warp w handles the 8 gate columns
// of k0=32r+2w, k0+1; lane owns a d-chunk of 8 (Wh in regs, packed f32x2).
// Fully distributed, predication-free gate phase:
//  - full-split butterfly leaves column q=(l>>2)&7's COMPLETE sum on lane l
//  - each lane applies ITS column's activation (sigmoid / tanh) BEFORE the
//    gather -> the serial post-gather chain is just c=fma; tanh(c); mul
//  - 4 shfl.idx gathers (base = l&16) give lanes 0-15 k0's activated gates
//    and lanes 16-31 k0+1's; ALL lanes redundantly compute c_state and nh
//    for their half (deterministic, no branch, no nh redistribution)
//  - exchange: lanes 0-7 each issue ONE st.shared::cluster.v2.f32 (k0,k0+1
//    are adjacent) to peer p -> 1 SASS store for all 16 values/warp; the
//    storing lane's barrier.cluster.arrive provides release ordering
//  - split arrive/wait with the y store + xc swap inside the window
// No DSMEM store after the final barrier (peer-exit race).
// ---------------------------------------------------------------------------
__global__ void __launch_bounds__(NTHR, 1) __cluster_dims__(CLUS, 1, 1)
rnn_kernel(const float* __restrict__ Wh,
           const int* __restrict__ seqlen,
           float* __restrict__ y) {
    __shared__ float h_s[2][HH];

    const int b = blockIdx.x / CLUS;
    const int r = blockIdx.x % CLUS;
    const int w = threadIdx.x >> 5;
    const int l = threadIdx.x & 31;
    const int k0 = r * 32 + 2 * w;

    // ---- preload Wh slice as packed f32x2 pairs over d ----
    // j<4: gate j of column k0 ; j>=4: gate j-4 of column k0+1
    unsigned long long wh2[8][4];
#pragma unroll
    for (int j = 0; j < 8; j++) {
        int col = (j < 4) ? (k0 + 256 * j) : (k0 + 1 + 256 * (j - 4));
#pragma unroll
        for (int dd = 0; dd < 4; dd++) {
            int d = l * 8 + dd * 2;
            float lo = Wh[(size_t)d * G4 + col];
            float hi = Wh[(size_t)(d + 1) * G4 + col];
            asm("mov.b64 %0, {%1, %2};" : "=l"(wh2[j][dd]) : "f"(lo), "f"(hi));
        }
    }

    // ---- zero initial hidden state (buffer 0) ----
    for (int i = threadIdx.x; i < HH; i += NTHR) h_s[0][i] = 0.f;
    __syncthreads();
    asm volatile("barrier.cluster.arrive.aligned;" ::: "memory");
    asm volatile("barrier.cluster.wait.aligned;"   ::: "memory");

    const int L = seqlen[b];
    const float* xWib = g_xWi + (size_t)b * TT * G4;
    float*       yb   = y + (size_t)b * TT * HH;

    // lanes 0-15 track k0's c_state, lanes 16-31 track k0+1's (redundant)
    const int myk = k0 + ((l >> 4) & 1);
    float c_state = 0.f;

    // DSMEM peer v2-store address: lane p<8 stores (k0,k0+1) to peer p
    unsigned int hs_addr;
    asm("{ .reg .u64 t; cvta.to.shared.u64 t, %1; cvt.u32.u64 %0, t; }"
        : "=r"(hs_addr) : "l"((void*)h_s));
    unsigned int st_peer;
    {
        unsigned int slot = hs_addr + (unsigned)k0 * 4u;   // 8B aligned
        asm("mapa.shared::cluster.u32 %0, %1, %2;"
            : "=r"(st_peer) : "r"(slot), "r"(l & 7));
    }

    // xWi column for loader lanes 0..7 (column c of this warp)
    const int c    = l & 7;
    const int gcol = (c < 4) ? (k0 + 256 * c) : (k0 + 1 + 256 * (c - 4));

    // preload xWi for t=0 (lanes 0..7: one LDG per warp)
    float xc = 0.f;
    if (l < 8) {
        int src0 = (TT - 1 + L) & (TT - 1);
        xc = xWib[(size_t)src0 * G4 + gcol];
    }

    const int  base   = l & 16;            // gather base for this half
    const int  gidx   = (l >> 2) & 3;      // gate index of my column
    const bool is_g   = (gidx == 2);       // candidate gate -> tanh
    const bool ystore = ((l & 15) == 0);   // lanes 0 and 16 write y

    for (int t = 0; t < TT; t++) {
        // prefetch next step's xWi (lanes 0..7, 1 LDG/warp)
        float xn = 0.f;
        if (l < 8 && t + 1 < TT) {
            int srcn = (TT - 2 - t + L) & (TT - 1);
            xn = xWib[(size_t)srcn * G4 + gcol];
        }

        // load previous h (own SMEM) as packed pairs
        const unsigned long long* hp =
            (const unsigned long long*)&h_s[t & 1][l * 8];
        unsigned long long h2[4];
        h2[0] = hp[0]; h2[1] = hp[1]; h2[2] = hp[2]; h2[3] = hp[3];

        // 8 packed-f32x2 accumulators (one per gate column)
        unsigned long long acc[8];
#pragma unroll
        for (int j = 0; j < 8; j++) acc[j] = 0ull;
#pragma unroll
        for (int dd = 0; dd < 4; dd++)
#pragma unroll
            for (int j = 0; j < 8; j++)
                asm("fma.rn.f32x2 %0, %1, %2, %0;"
                    : "+l"(acc[j]) : "l"(h2[dd]), "l"(wh2[j][dd]));

        // horizontal pair-sum -> ps[8]
        float ps[8];
#pragma unroll
        for (int j = 0; j < 8; j++) {
            float lo, hi;
            asm("mov.b64 {%0, %1}, %2;" : "=f"(lo), "=f"(hi) : "l"(acc[j]));
            ps[j] = lo + hi;
        }

        // full-split butterfly: 16 SHFL, 5 levels -> quad q holds column q
        float u0, u1, u2, u3;
        {
            float a0 = __shfl_xor_sync(0xffffffffu, ps[0], 16);
            float a4 = __shfl_xor_sync(0xffffffffu, ps[4], 16);
            float a1 = __shfl_xor_sync(0xffffffffu, ps[1], 16);
            float a5 = __shfl_xor_sync(0xffffffffu, ps[5], 16);
            float a2 = __shfl_xor_sync(0xffffffffu, ps[2], 16);
            float a6 = __shfl_xor_sync(0xffffffffu, ps[6], 16);
            float a3 = __shfl_xor_sync(0xffffffffu, ps[3], 16);
            float a7 = __shfl_xor_sync(0xffffffffu, ps[7], 16);
            bool hi = (l & 16);
            u0 = hi ? (ps[4] + a4) : (ps[0] + a0);
            u1 = hi ? (ps[5] + a5) : (ps[1] + a1);
            u2 = hi ? (ps[6] + a6) : (ps[2] + a2);
            u3 = hi ? (ps[7] + a7) : (ps[3] + a3);
        }
        float t0, t1;
        {
            float a0 = __shfl_xor_sync(0xffffffffu, u0, 8);
            float a2 = __shfl_xor_sync(0xffffffffu, u2, 8);
            float a1 = __shfl_xor_sync(0xffffffffu, u1, 8);
            float a3 = __shfl_xor_sync(0xffffffffu, u3, 8);
            bool hi = (l & 8);
            t0 = hi ? (u2 + a2) : (u0 + a0);
            t1 = hi ? (u3 + a3) : (u1 + a1);
        }
        float s;
        {
            float a0 = __shfl_xor_sync(0xffffffffu, t0, 4);
            float a1 = __shfl_xor_sync(0xffffffffu, t1, 4);
            s = (l & 4) ? (t1 + a1) : (t0 + a0);
        }
        s += __shfl_xor_sync(0xffffffffu, s, 2);
        s += __shfl_xor_sync(0xffffffffu, s, 1);

        // add xWi pre-activation (route from loader lane = my quad index)
        float xq = __shfl_sync(0xffffffffu, xc, (l >> 2) & 7);
        s += xq;

        // distributed activation of MY column: sigmoid for i,f,o; tanh for g
        float arg = is_g ? (2.f * s) : s;
        float e   = __expf(-arg);
        float sg  = __fdividef(1.f, 1.f + e);
        float act = is_g ? fmaf(2.f, sg, -1.f) : sg;

        // gather activated gates of my half's h-index (base 0 -> k0, 16 -> k0+1)
        float g0 = __shfl_sync(0xffffffffu, act, base + 0);
        float g1 = __shfl_sync(0xffffffffu, act, base + 4);
        float g2 = __shfl_sync(0xffffffffu, act, base + 8);
        float g3 = __shfl_sync(0xffffffffu, act, base + 12);

        // all lanes: LSTM cell update for their half (redundant, branch-free)
        c_state = fmaf(g1, c_state, g0 * g2);
        float e2 = __expf(-2.f * c_state);
        float tc = fmaf(2.f, __fdividef(1.f, 1.f + e2), -1.f);
        float nh = g3 * tc;

        // other half's nh (k0+1 for lanes 0-15) for the paired v2 store
        float nho = __shfl_sync(0xffffffffu, nh, l | 16);

        // exchange: lanes 0-7 store (nh_k0, nh_k1) to peer p — one SASS
        // instruction for all 16 values. Never on the last step.
        if (t < TT - 1 && l < 8) {
            unsigned int dst =
                st_peer + (((t + 1) & 1) ? (unsigned)HH * 4u : 0u);
            asm volatile("st.shared::cluster.v2.f32 [%0], {%1, %2};"
                         :: "r"(dst), "f"(nh), "f"(nho) : "memory");
        }

        if (t < TT - 1)
            asm volatile("barrier.cluster.arrive.aligned;" ::: "memory");

        // inside the barrier window: y store + register swap
        if (ystore) {
            const int src = (TT - 1 - t + L) & (TT - 1);
            yb[(size_t)src * HH + myk] = nh;
        }
        xc = xn;

        if (t < TT - 1)
            asm volatile("barrier.cluster.wait.aligned;" ::: "memory");
    }
}

// ---------------------------------------------------------------------------
extern "C" void kernel_launch(void* const* d_in, const int* in_sizes, int n_in,
                              void* d_out, int out_size) {
    const float* x    = (const float*)d_in[0];
    const float* Wi   = (const float*)d_in[1];
    const float* Wh   = (const float*)d_in[2];
    const float* bias = (const float*)d_in[3];
    const int*   seql = (const int*)d_in[4];
    float*       y    = (float*)d_out;

    gemm_kernel<<<dim3(G4 / 64, (BB * TT) / 128), 256>>>(x, Wi, bias);
    rnn_kernel<<<BB * CLUS, NTHR>>>(Wh, seql, y);
}